// round 9
// baseline (speedup 1.0000x reference)
#include <cuda_runtime.h>

#define D     256
#define SEQ   128
#define BATCH 32

typedef unsigned long long ull;

// Packed f32x2 ops (sm_100+; FFMA2/FADD2 reachable only via PTX)
#define FMA_F32X2(d, a, b, c) \
    asm("fma.rn.f32x2 %0, %1, %2, %3;" : "=l"(d) : "l"(a), "l"(b), "l"(c))
#define ADD_F32X2(d, a, b) \
    asm("add.rn.f32x2 %0, %1, %2;" : "=l"(d) : "l"(a), "l"(b))
#define DUP_F32X2(d, x) \
    asm("mov.b64 %0, {%1, %1};" : "=l"(d) : "r"(__float_as_uint(x)))

union F2U { ull u; float2 f; };

__device__ float g_pooled[BATCH * D];   // only scratch left (32 KB)

// ---------------------------------------------------------------------------
// Fused kernel: gather + dual GEMM + pair pooling.
// Block = (batch b, 32-dim chunk d0). Computes Xl[128x32], Xr[128x32] with a
// combined 64-col B tile [Wl|Wr], deposits results directly in pooling layout
// (Ls[i][d], Rs[d][i]), then pools:
//   pooled[d] = 0.5*( S*(sumL+sumR) + sum_ij |l_i + r_j| )   (relu=(x+|x|)/2)
// ---------------------------------------------------------------------------
#define BK 16
#define AS_STRIDE 260   // 2*128+4 floats; rows 1040 B (16B-aligned)
#define BS_STRIDE 68    // 64+4 floats;    rows 272 B (16B-aligned)
#define LS_STRIDE 34    // 32+2
#define RS_STRIDE 130   // 128+2

struct GemmSm { float As2[BK][AS_STRIDE]; float Bs[BK][BS_STRIDE]; };
struct PoolSm {
    float Ls[SEQ][LS_STRIDE];   // [i][d]
    float Rs[32][RS_STRIDE];    // [d][j] transposed
    float red[8][32];
    float sLR[2][32];
};
union SmemU { GemmSm g; PoolSm p; };

__global__ __launch_bounds__(256, 2) void k_main(
    const int*   __restrict__ X,
    const float* __restrict__ emb,
    const float* __restrict__ Wl, const float* __restrict__ bl,
    const float* __restrict__ Wr, const float* __restrict__ br)
{
    __shared__ SmemU sm;
    __shared__ int rowidx[SEQ];

    const int t  = threadIdx.x;
    const int b  = blockIdx.y;
    const int d0 = blockIdx.x * 32;

    if (t < SEQ) rowidx[t] = X[b * SEQ + t];
    __syncthreads();

    const int mi = (t >> 4) * 8;   // 8 rows: mi..mi+7
    const int ni = (t & 15) * 4;   // 4 cols of combined [l:0..31 | r:32..63]

    ull c2[8][2];
#pragma unroll
    for (int i = 0; i < 8; i++) { c2[i][0] = 0ULL; c2[i][1] = 0ULL; }

    for (int k0 = 0; k0 < D; k0 += BK) {
        // A tile (gathered, duplicated {a,a} for FFMA2): 128x16
#pragma unroll
        for (int q = 0; q < 8; q++) {
            int li = t + 256 * q;          // 0..2047
            int m  = li >> 4;
            int k  = li & 15;
            float v = emb[(size_t)rowidx[m] * D + (k0 + k)];
            sm.g.As2[k][2 * m]     = v;
            sm.g.As2[k][2 * m + 1] = v;
        }
        // B tile: 16 x [Wl(32) | Wr(32)]
#pragma unroll
        for (int q = 0; q < 4; q++) {
            int li = t + 256 * q;          // 0..1023
            int n  = li >> 4;              // 0..63
            int k  = li & 15;
            const float* Wp = (n < 32) ? (Wl + (size_t)(d0 + n) * D)
                                       : (Wr + (size_t)(d0 + n - 32) * D);
            sm.g.Bs[k][n] = Wp[k0 + k];
        }
        __syncthreads();

#pragma unroll
        for (int kk = 0; kk < BK; kk++) {
            ulonglong2 a01 = *(const ulonglong2*)&sm.g.As2[kk][2 * mi];
            ulonglong2 a23 = *(const ulonglong2*)&sm.g.As2[kk][2 * mi + 4];
            ulonglong2 a45 = *(const ulonglong2*)&sm.g.As2[kk][2 * mi + 8];
            ulonglong2 a67 = *(const ulonglong2*)&sm.g.As2[kk][2 * mi + 12];
            ulonglong2 bv  = *(const ulonglong2*)&sm.g.Bs[kk][ni];
            ull a[8] = {a01.x, a01.y, a23.x, a23.y, a45.x, a45.y, a67.x, a67.y};
#pragma unroll
            for (int i = 0; i < 8; i++) {
                FMA_F32X2(c2[i][0], a[i], bv.x, c2[i][0]);
                FMA_F32X2(c2[i][1], a[i], bv.y, c2[i][1]);
            }
        }
        __syncthreads();   // also protects the GEMM->pool smem repurposing
    }

    // Epilogue: add bias, deposit into pooling layout.
    const bool isL = (ni < 32);
    const int  dd  = isL ? ni : (ni - 32);
    const float* bb = isL ? bl : br;
    float4 bias = *(const float4*)&bb[d0 + dd];

#pragma unroll
    for (int i = 0; i < 8; i++) {
        int row = mi + i;
        F2U p0, p1; p0.u = c2[i][0]; p1.u = c2[i][1];
        float v0 = p0.f.x + bias.x;
        float v1 = p0.f.y + bias.y;
        float v2 = p1.f.x + bias.z;
        float v3 = p1.f.y + bias.w;
        if (isL) {
            sm.p.Ls[row][dd]     = v0;
            sm.p.Ls[row][dd + 1] = v1;
            sm.p.Ls[row][dd + 2] = v2;
            sm.p.Ls[row][dd + 3] = v3;
        } else {
            sm.p.Rs[dd][row]     = v0;
            sm.p.Rs[dd + 1][row] = v1;
            sm.p.Rs[dd + 2][row] = v2;
            sm.p.Rs[dd + 3][row] = v3;
        }
    }
    __syncthreads();

    // ---- Pooling ----
    const int d  = t & 31;
    const int jg = t >> 5;                 // 0..7, 16 j's each

    ull r2[8];
#pragma unroll
    for (int jj = 0; jj < 8; jj++)
        r2[jj] = *(const ull*)&sm.p.Rs[d][jg * 16 + 2 * jj];

    const ull ABSMASK = 0x7FFFFFFF7FFFFFFFULL;
    ull acc[4] = {0ULL, 0ULL, 0ULL, 0ULL};

#pragma unroll 2
    for (int i = 0; i < SEQ; i++) {
        ull l2; DUP_F32X2(l2, sm.p.Ls[i][d]);
#pragma unroll
        for (int jj = 0; jj < 8; jj++) {
            ull s;
            ADD_F32X2(s, l2, r2[jj]);
            s &= ABSMASK;                          // packed |.| (alu pipe)
            ADD_F32X2(acc[jj & 3], acc[jj & 3], s);
        }
    }

    float asum = 0.f;
#pragma unroll
    for (int q = 0; q < 4; q++) {
        F2U u; u.u = acc[q];
        asum += u.f.x + u.f.y;
    }
    sm.p.red[jg][d] = asum;

    if (t < 32) {                          // sumL (warp 0)
        float s = 0.f;
#pragma unroll 8
        for (int i = 0; i < SEQ; i++) s += sm.p.Ls[i][t];
        sm.p.sLR[0][t] = s;
    } else if (t < 64) {                   // sumR (warp 1)
        int dq = t - 32;
        float s = 0.f;
#pragma unroll 8
        for (int j = 0; j < SEQ; j++) s += sm.p.Rs[dq][j];
        sm.p.sLR[1][dq] = s;
    }
    __syncthreads();

    if (t < 32) {
        float a = 0.f;
#pragma unroll
        for (int g = 0; g < 8; g++) a += sm.p.red[g][t];
        float lin = (float)SEQ * (sm.p.sLR[0][t] + sm.p.sLR[1][t]);
        g_pooled[b * D + d0 + t] = 0.5f * (lin + a);
    }
}

// ---------------------------------------------------------------------------
// out[b,:] = pooled[b,:] @ W_rn.T + (128*128) * b_rn
// ---------------------------------------------------------------------------
__global__ __launch_bounds__(256) void k_out(
    const float* __restrict__ Wrn, const float* __restrict__ brn,
    float* __restrict__ out)
{
    __shared__ float p[D];
    const int b = blockIdx.x;
    const int t = threadIdx.x;

    p[t] = g_pooled[b * D + t];
    __syncthreads();

    float acc = 16384.f * brn[t];
    const float4* w = (const float4*)(Wrn + (size_t)t * D);
#pragma unroll 8
    for (int k = 0; k < D / 4; k++) {
        float4 wv = w[k];
        acc += p[4 * k + 0] * wv.x + p[4 * k + 1] * wv.y
             + p[4 * k + 2] * wv.z + p[4 * k + 3] * wv.w;
    }
    out[b * D + t] = acc;
}

// ---------------------------------------------------------------------------
extern "C" void kernel_launch(void* const* d_in, const int* in_sizes, int n_in,
                              void* d_out, int out_size)
{
    const int*   X   = (const int*)  d_in[0];
    const float* emb = (const float*)d_in[1];
    const float* Wl  = (const float*)d_in[2];
    const float* bl  = (const float*)d_in[3];
    const float* Wr  = (const float*)d_in[4];
    const float* br  = (const float*)d_in[5];
    const float* Wrn = (const float*)d_in[6];
    const float* brn = (const float*)d_in[7];
    float* out = (float*)d_out;

    k_main<<<dim3(D / 32, BATCH), 256>>>(X, emb, Wl, bl, Wr, br);
    k_out<<<BATCH, 256>>>(Wrn, brn, out);
}

// round 11
// speedup vs baseline: 1.4168x; 1.4168x over previous
#include <cuda_runtime.h>

#define D     256
#define SEQ   128
#define BATCH 32

typedef unsigned long long ull;

// Packed f32x2 ops (sm_100+; FFMA2 reachable only via PTX)
#define FMA_F32X2(d, a, b, c) \
    asm("fma.rn.f32x2 %0, %1, %2, %3;" : "=l"(d) : "l"(a), "l"(b), "l"(c))
#define ADD_F32X2(d, a, b) \
    asm("add.rn.f32x2 %0, %1, %2;" : "=l"(d) : "l"(a), "l"(b))
#define DUP_F32X2(d, x) \
    asm("mov.b64 %0, {%1, %1};" : "=l"(d) : "r"(__float_as_uint(x)))
#define PACK_F32X2(d, lo, hi) \
    asm("mov.b64 %0, {%1, %2};" : "=l"(d) : "r"(__float_as_uint(lo)), "r"(__float_as_uint(hi)))

union F2U { ull u; float2 f; };

__device__ float g_pooled[BATCH * D];   // only scratch (32 KB)

// ---------------------------------------------------------------------------
// Fused kernel: gather + dual GEMM + pair pooling.
// GEMM uses diagonal FFMA2 packing: no operand duplication in smem.
//   cd[i][p][0] += {A[m],A[m+1]} * {B[n],B[n+1]}   -> {C[m][n],   C[m+1][n+1]}
//   cd[i][p][1] += {A[m],A[m+1]} * {B[n+1],B[n]}   -> {C[m][n+1], C[m+1][n]}
// Pool: pooled[d] = 0.5*( S*(sumL+sumR) + sum_ij |l_i + r_j| )
// ---------------------------------------------------------------------------
#define BK 16
#define AS_STRIDE 132   // 128+4 floats (un-duplicated now)
#define BS_STRIDE 68    // 64+4
#define LS_STRIDE 34    // 32+2
#define RS_STRIDE 130   // 128+2

struct GemmSm { float As[BK][AS_STRIDE]; float Bs[BK][BS_STRIDE]; };
struct PoolSm {
    float Ls[SEQ][LS_STRIDE];   // [i][d]
    float Rs[32][RS_STRIDE];    // [d][j] transposed
    float red[8][32];
    float sLR[2][32];
};
union SmemU { GemmSm g; PoolSm p; };

__global__ __launch_bounds__(256, 2) void k_main(
    const int*   __restrict__ X,
    const float* __restrict__ emb,
    const float* __restrict__ Wl, const float* __restrict__ bl,
    const float* __restrict__ Wr, const float* __restrict__ br)
{
    __shared__ SmemU sm;
    __shared__ int rowidx[SEQ];

    const int t  = threadIdx.x;
    const int b  = blockIdx.y;
    const int d0 = blockIdx.x * 32;

    if (t < SEQ) rowidx[t] = X[b * SEQ + t];
    __syncthreads();

    const int mi = (t >> 4) * 8;   // rows mi..mi+7
    const int ni = (t & 15) * 4;   // cols of combined [l:0..31 | r:32..63]

    // fill-phase indices (float4 granularity)
    const int fa_m0  = (t + 0)   >> 2, fa_k0 = ((t + 0)   & 3) * 4;
    const int fa_m1  = (t + 256) >> 2, fa_k1 = ((t + 256) & 3) * 4;
    const int fb_n   = t >> 2,         fb_k  = (t & 3) * 4;
    const float* WpB = (fb_n < 32) ? (Wl + (size_t)(d0 + fb_n) * D)
                                   : (Wr + (size_t)(d0 + fb_n - 32) * D);

    ull cd[4][2][2];
#pragma unroll
    for (int i = 0; i < 4; i++)
#pragma unroll
        for (int p = 0; p < 2; p++) { cd[i][p][0] = 0ULL; cd[i][p][1] = 0ULL; }

    for (int k0 = 0; k0 < D; k0 += BK) {
        // A tile: 128x16, gathered, float4 loads (2/thread)
        {
            float4 v0 = *(const float4*)&emb[(size_t)rowidx[fa_m0] * D + k0 + fa_k0];
            float4 v1 = *(const float4*)&emb[(size_t)rowidx[fa_m1] * D + k0 + fa_k1];
            sm.g.As[fa_k0 + 0][fa_m0] = v0.x; sm.g.As[fa_k0 + 1][fa_m0] = v0.y;
            sm.g.As[fa_k0 + 2][fa_m0] = v0.z; sm.g.As[fa_k0 + 3][fa_m0] = v0.w;
            sm.g.As[fa_k1 + 0][fa_m1] = v1.x; sm.g.As[fa_k1 + 1][fa_m1] = v1.y;
            sm.g.As[fa_k1 + 2][fa_m1] = v1.z; sm.g.As[fa_k1 + 3][fa_m1] = v1.w;
        }
        // B tile: 16 x [Wl(32)|Wr(32)], float4 loads (1/thread)
        {
            float4 v = *(const float4*)&WpB[k0 + fb_k];
            sm.g.Bs[fb_k + 0][fb_n] = v.x; sm.g.Bs[fb_k + 1][fb_n] = v.y;
            sm.g.Bs[fb_k + 2][fb_n] = v.z; sm.g.Bs[fb_k + 3][fb_n] = v.w;
        }
        __syncthreads();

#pragma unroll
        for (int kk = 0; kk < BK; kk++) {
            float4 a0v = *(const float4*)&sm.g.As[kk][mi];
            float4 a1v = *(const float4*)&sm.g.As[kk][mi + 4];
            float4 bv  = *(const float4*)&sm.g.Bs[kk][ni];
            ull aP[4], bf0, bf1, br0, br1;
            PACK_F32X2(aP[0], a0v.x, a0v.y);
            PACK_F32X2(aP[1], a0v.z, a0v.w);
            PACK_F32X2(aP[2], a1v.x, a1v.y);
            PACK_F32X2(aP[3], a1v.z, a1v.w);
            PACK_F32X2(bf0, bv.x, bv.y);
            PACK_F32X2(bf1, bv.z, bv.w);
            PACK_F32X2(br0, bv.y, bv.x);
            PACK_F32X2(br1, bv.w, bv.z);
#pragma unroll
            for (int i = 0; i < 4; i++) {
                FMA_F32X2(cd[i][0][0], aP[i], bf0, cd[i][0][0]);
                FMA_F32X2(cd[i][0][1], aP[i], br0, cd[i][0][1]);
                FMA_F32X2(cd[i][1][0], aP[i], bf1, cd[i][1][0]);
                FMA_F32X2(cd[i][1][1], aP[i], br1, cd[i][1][1]);
            }
        }
        __syncthreads();   // also protects the GEMM->pool smem repurposing
    }

    // Epilogue: un-diagonalize, add bias, deposit into pooling layout.
    const bool isL = (ni < 32);
    const int  dd  = isL ? ni : (ni - 32);
    const float* bb = isL ? bl : br;
    float4 bias = *(const float4*)&bb[d0 + dd];

#pragma unroll
    for (int i = 0; i < 4; i++) {
        int rA = mi + 2 * i, rB = rA + 1;
        F2U d00, d01, d10, d11;
        d00.u = cd[i][0][0]; d01.u = cd[i][0][1];
        d10.u = cd[i][1][0]; d11.u = cd[i][1][1];
        float a0 = d00.f.x + bias.x;   // C[rA][dd+0]
        float a1 = d01.f.x + bias.y;   // C[rA][dd+1]
        float a2 = d10.f.x + bias.z;   // C[rA][dd+2]
        float a3 = d11.f.x + bias.w;   // C[rA][dd+3]
        float b0 = d01.f.y + bias.x;   // C[rB][dd+0]
        float b1 = d00.f.y + bias.y;   // C[rB][dd+1]
        float b2 = d11.f.y + bias.z;   // C[rB][dd+2]
        float b3 = d10.f.y + bias.w;   // C[rB][dd+3]
        if (isL) {
            sm.p.Ls[rA][dd] = a0; sm.p.Ls[rA][dd + 1] = a1;
            sm.p.Ls[rA][dd + 2] = a2; sm.p.Ls[rA][dd + 3] = a3;
            sm.p.Ls[rB][dd] = b0; sm.p.Ls[rB][dd + 1] = b1;
            sm.p.Ls[rB][dd + 2] = b2; sm.p.Ls[rB][dd + 3] = b3;
        } else {
            sm.p.Rs[dd][rA] = a0; sm.p.Rs[dd + 1][rA] = a1;
            sm.p.Rs[dd + 2][rA] = a2; sm.p.Rs[dd + 3][rA] = a3;
            sm.p.Rs[dd][rB] = b0; sm.p.Rs[dd + 1][rB] = b1;
            sm.p.Rs[dd + 2][rB] = b2; sm.p.Rs[dd + 3][rB] = b3;
        }
    }
    __syncthreads();

    // ---- Pooling ----
    const int d  = t & 31;
    const int jg = t >> 5;                 // 0..7, 16 j's each

    ull r2[8];
#pragma unroll
    for (int jj = 0; jj < 8; jj++)
        r2[jj] = *(const ull*)&sm.p.Rs[d][jg * 16 + 2 * jj];

    const ull ABSMASK = 0x7FFFFFFF7FFFFFFFULL;
    ull acc[4] = {0ULL, 0ULL, 0ULL, 0ULL};

#pragma unroll 2
    for (int i = 0; i < SEQ; i++) {
        ull l2; DUP_F32X2(l2, sm.p.Ls[i][d]);
#pragma unroll
        for (int jj = 0; jj < 8; jj++) {
            ull s;
            ADD_F32X2(s, l2, r2[jj]);
            s &= ABSMASK;                          // packed |.| (alu pipe)
            ADD_F32X2(acc[jj & 3], acc[jj & 3], s);
        }
    }

    float asum = 0.f;
#pragma unroll
    for (int q = 0; q < 4; q++) {
        F2U u; u.u = acc[q];
        asum += u.f.x + u.f.y;
    }
    sm.p.red[jg][d] = asum;

    if (t < 32) {                          // sumL (warp 0)
        float s = 0.f;
#pragma unroll 8
        for (int i = 0; i < SEQ; i++) s += sm.p.Ls[i][t];
        sm.p.sLR[0][t] = s;
    } else if (t < 64) {                   // sumR (warp 1)
        int dq = t - 32;
        float s = 0.f;
#pragma unroll 8
        for (int j = 0; j < SEQ; j++) s += sm.p.Rs[dq][j];
        sm.p.sLR[1][dq] = s;
    }
    __syncthreads();

    if (t < 32) {
        float a = 0.f;
#pragma unroll
        for (int g = 0; g < 8; g++) a += sm.p.red[g][t];
        float lin = (float)SEQ * (sm.p.sLR[0][t] + sm.p.sLR[1][t]);
        g_pooled[b * D + d0 + t] = 0.5f * (lin + a);
    }
}

// ---------------------------------------------------------------------------
// out[b,o] = pooled[b,:] . Wrn[o,:] + 16384*brn[o]
// grid (8, 32): block = (32-output chunk, batch). thread = (o_local, k_slice).
// 8-way k-split + shfl reduce: 8x the parallelism of the old version.
// ---------------------------------------------------------------------------
__global__ __launch_bounds__(256) void k_out(
    const float* __restrict__ Wrn, const float* __restrict__ brn,
    float* __restrict__ out)
{
    __shared__ float p[D];
    const int b  = blockIdx.y;
    const int oc = blockIdx.x;
    const int t  = threadIdx.x;

    p[t] = g_pooled[b * D + t];
    __syncthreads();

    const int ol = t >> 3;          // 0..31
    const int ks = t & 7;           // 0..7
    const int o  = oc * 32 + ol;

    const float4* w = (const float4*)(Wrn + (size_t)o * D + ks * 32);
    float acc = 0.f;
#pragma unroll
    for (int u = 0; u < 8; u++) {
        float4 wv = w[u];
        int kb = ks * 32 + u * 4;
        acc += p[kb + 0] * wv.x + p[kb + 1] * wv.y
             + p[kb + 2] * wv.z + p[kb + 3] * wv.w;
    }
    acc += __shfl_xor_sync(0xffffffffu, acc, 1);
    acc += __shfl_xor_sync(0xffffffffu, acc, 2);
    acc += __shfl_xor_sync(0xffffffffu, acc, 4);

    if (ks == 0)
        out[b * D + o] = acc + 16384.f * brn[o];
}

// ---------------------------------------------------------------------------
extern "C" void kernel_launch(void* const* d_in, const int* in_sizes, int n_in,
                              void* d_out, int out_size)
{
    const int*   X   = (const int*)  d_in[0];
    const float* emb = (const float*)d_in[1];
    const float* Wl  = (const float*)d_in[2];
    const float* bl  = (const float*)d_in[3];
    const float* Wr  = (const float*)d_in[4];
    const float* br  = (const float*)d_in[5];
    const float* Wrn = (const float*)d_in[6];
    const float* brn = (const float*)d_in[7];
    float* out = (float*)d_out;

    k_main<<<dim3(D / 32, BATCH), 256>>>(X, emb, Wl, bl, Wr, br);
    k_out<<<dim3(8, BATCH), 256>>>(Wrn, brn, out);
}

// round 13
// speedup vs baseline: 1.5864x; 1.1197x over previous
#include <cuda_runtime.h>

#define D     256
#define SEQ   128
#define BATCH 32

typedef unsigned long long ull;

// Packed f32x2 ops (sm_100+; FFMA2 reachable only via PTX)
#define FMA_F32X2(d, a, b, c) \
    asm("fma.rn.f32x2 %0, %1, %2, %3;" : "=l"(d) : "l"(a), "l"(b), "l"(c))
#define ADD_F32X2(d, a, b) \
    asm("add.rn.f32x2 %0, %1, %2;" : "=l"(d) : "l"(a), "l"(b))
#define DUP_F32X2(d, x) \
    asm("mov.b64 %0, {%1, %1};" : "=l"(d) : "r"(__float_as_uint(x)))
#define PACK_F32X2(d, lo, hi) \
    asm("mov.b64 %0, {%1, %2};" : "=l"(d) : "r"(__float_as_uint(lo)), "r"(__float_as_uint(hi)))

union F2U { ull u; float2 f; };

// ---------------------------------------------------------------------------
// k_init: out[b,o] = 16384 * brn[o]  (atomic accumulation base for k_main)
// ---------------------------------------------------------------------------
__global__ __launch_bounds__(256) void k_init(
    const float* __restrict__ brn, float* __restrict__ out)
{
    int i = blockIdx.x * 256 + threadIdx.x;     // 0..8191
    out[i] = 16384.f * brn[i & (D - 1)];
}

// ---------------------------------------------------------------------------
// Fused kernel: gather + dual GEMM (diagonal FFMA2, double-buffered tiles)
// + pair pooling + rank-32 update of the output GEMV via atomics.
//   pooled[d] = 0.5*( S*(sumL+sumR) + sum_ij |l_i + r_j| )
//   out[b,o] += sum_dd pooled[d0+dd] * Wrn[o][d0+dd]
// ---------------------------------------------------------------------------
#define BK 16
#define AS_STRIDE 132   // 128+4 floats
#define BS_STRIDE 68    // 64+4
#define LS_STRIDE 34    // 32+2
#define RS_STRIDE 130   // 128+2

struct GemmSm { float As[2][BK][AS_STRIDE]; float Bs[2][BK][BS_STRIDE]; };
struct PoolSm {
    float Ls[SEQ][LS_STRIDE];   // [i][d]
    float Rs[32][RS_STRIDE];    // [d][j] transposed
    float red[8][32];
    float sLR[2][32];
};
union SmemU { GemmSm g; PoolSm p; };

__global__ __launch_bounds__(256, 2) void k_main(
    const int*   __restrict__ X,
    const float* __restrict__ emb,
    const float* __restrict__ Wl, const float* __restrict__ bl,
    const float* __restrict__ Wr, const float* __restrict__ br,
    const float* __restrict__ Wrn,
    float* __restrict__ out)
{
    __shared__ SmemU sm;
    __shared__ int rowidx[SEQ];

    const int t  = threadIdx.x;
    const int b  = blockIdx.y;
    const int d0 = blockIdx.x * 32;

    if (t < SEQ) rowidx[t] = X[b * SEQ + t];
    __syncthreads();

    const int mi = (t >> 4) * 8;   // rows mi..mi+7
    const int ni = (t & 15) * 4;   // cols of combined [l:0..31 | r:32..63]

    // fill-phase indices (float4 granularity)
    const int fa_m0  = (t + 0)   >> 2, fa_k0 = ((t + 0)   & 3) * 4;
    const int fa_m1  = (t + 256) >> 2, fa_k1 = ((t + 256) & 3) * 4;
    const int fb_n   = t >> 2,         fb_k  = (t & 3) * 4;
    const float* WpB = (fb_n < 32) ? (Wl + (size_t)(d0 + fb_n) * D)
                                   : (Wr + (size_t)(d0 + fb_n - 32) * D);
    const float* embA0 = emb + (size_t)rowidx[fa_m0] * D + fa_k0;
    const float* embA1 = emb + (size_t)rowidx[fa_m1] * D + fa_k1;

    ull cd[4][2][2];
#pragma unroll
    for (int i = 0; i < 4; i++)
#pragma unroll
        for (int p = 0; p < 2; p++) { cd[i][p][0] = 0ULL; cd[i][p][1] = 0ULL; }

    // Prefetch tile 0 and stage it.
    float4 pa0 = *(const float4*)&embA0[0];
    float4 pa1 = *(const float4*)&embA1[0];
    float4 pb  = *(const float4*)&WpB[fb_k];
    {
        sm.g.As[0][fa_k0 + 0][fa_m0] = pa0.x; sm.g.As[0][fa_k0 + 1][fa_m0] = pa0.y;
        sm.g.As[0][fa_k0 + 2][fa_m0] = pa0.z; sm.g.As[0][fa_k0 + 3][fa_m0] = pa0.w;
        sm.g.As[0][fa_k1 + 0][fa_m1] = pa1.x; sm.g.As[0][fa_k1 + 1][fa_m1] = pa1.y;
        sm.g.As[0][fa_k1 + 2][fa_m1] = pa1.z; sm.g.As[0][fa_k1 + 3][fa_m1] = pa1.w;
        sm.g.Bs[0][fb_k + 0][fb_n] = pb.x; sm.g.Bs[0][fb_k + 1][fb_n] = pb.y;
        sm.g.Bs[0][fb_k + 2][fb_n] = pb.z; sm.g.Bs[0][fb_k + 3][fb_n] = pb.w;
    }
    __syncthreads();

#pragma unroll 1
    for (int tile = 0; tile < D / BK; tile++) {
        const int buf = tile & 1;
        // Prefetch next tile into registers (overlaps with MACs below).
        if (tile < D / BK - 1) {
            int k0n = (tile + 1) * BK;
            pa0 = *(const float4*)&embA0[k0n];
            pa1 = *(const float4*)&embA1[k0n];
            pb  = *(const float4*)&WpB[k0n + fb_k];
        }

#pragma unroll
        for (int kk = 0; kk < BK; kk++) {
            float4 a0v = *(const float4*)&sm.g.As[buf][kk][mi];
            float4 a1v = *(const float4*)&sm.g.As[buf][kk][mi + 4];
            float4 bv  = *(const float4*)&sm.g.Bs[buf][kk][ni];
            ull aP[4], bf0, bf1, br0, br1;
            PACK_F32X2(aP[0], a0v.x, a0v.y);
            PACK_F32X2(aP[1], a0v.z, a0v.w);
            PACK_F32X2(aP[2], a1v.x, a1v.y);
            PACK_F32X2(aP[3], a1v.z, a1v.w);
            PACK_F32X2(bf0, bv.x, bv.y);
            PACK_F32X2(bf1, bv.z, bv.w);
            PACK_F32X2(br0, bv.y, bv.x);
            PACK_F32X2(br1, bv.w, bv.z);
#pragma unroll
            for (int i = 0; i < 4; i++) {
                FMA_F32X2(cd[i][0][0], aP[i], bf0, cd[i][0][0]);
                FMA_F32X2(cd[i][0][1], aP[i], br0, cd[i][0][1]);
                FMA_F32X2(cd[i][1][0], aP[i], bf1, cd[i][1][0]);
                FMA_F32X2(cd[i][1][1], aP[i], br1, cd[i][1][1]);
            }
        }

        // Stage next tile into the other buffer.
        if (tile < D / BK - 1) {
            const int nb = buf ^ 1;
            sm.g.As[nb][fa_k0 + 0][fa_m0] = pa0.x; sm.g.As[nb][fa_k0 + 1][fa_m0] = pa0.y;
            sm.g.As[nb][fa_k0 + 2][fa_m0] = pa0.z; sm.g.As[nb][fa_k0 + 3][fa_m0] = pa0.w;
            sm.g.As[nb][fa_k1 + 0][fa_m1] = pa1.x; sm.g.As[nb][fa_k1 + 1][fa_m1] = pa1.y;
            sm.g.As[nb][fa_k1 + 2][fa_m1] = pa1.z; sm.g.As[nb][fa_k1 + 3][fa_m1] = pa1.w;
            sm.g.Bs[nb][fb_k + 0][fb_n] = pb.x; sm.g.Bs[nb][fb_k + 1][fb_n] = pb.y;
            sm.g.Bs[nb][fb_k + 2][fb_n] = pb.z; sm.g.Bs[nb][fb_k + 3][fb_n] = pb.w;
            __syncthreads();
        }
    }
    __syncthreads();   // all MAC reads done before smem repurposed for pooling

    // Epilogue: un-diagonalize, add bias, deposit into pooling layout.
    const bool isL = (ni < 32);
    const int  dd  = isL ? ni : (ni - 32);
    const float* bb = isL ? bl : br;
    float4 bias = *(const float4*)&bb[d0 + dd];

#pragma unroll
    for (int i = 0; i < 4; i++) {
        int rA = mi + 2 * i, rB = rA + 1;
        F2U d00, d01, d10, d11;
        d00.u = cd[i][0][0]; d01.u = cd[i][0][1];
        d10.u = cd[i][1][0]; d11.u = cd[i][1][1];
        float a0 = d00.f.x + bias.x;   // C[rA][dd+0]
        float a1 = d01.f.x + bias.y;   // C[rA][dd+1]
        float a2 = d10.f.x + bias.z;   // C[rA][dd+2]
        float a3 = d11.f.x + bias.w;   // C[rA][dd+3]
        float b0 = d01.f.y + bias.x;   // C[rB][dd+0]
        float b1 = d00.f.y + bias.y;   // C[rB][dd+1]
        float b2 = d11.f.y + bias.z;   // C[rB][dd+2]
        float b3 = d10.f.y + bias.w;   // C[rB][dd+3]
        if (isL) {
            sm.p.Ls[rA][dd] = a0; sm.p.Ls[rA][dd + 1] = a1;
            sm.p.Ls[rA][dd + 2] = a2; sm.p.Ls[rA][dd + 3] = a3;
            sm.p.Ls[rB][dd] = b0; sm.p.Ls[rB][dd + 1] = b1;
            sm.p.Ls[rB][dd + 2] = b2; sm.p.Ls[rB][dd + 3] = b3;
        } else {
            sm.p.Rs[dd][rA] = a0; sm.p.Rs[dd + 1][rA] = a1;
            sm.p.Rs[dd + 2][rA] = a2; sm.p.Rs[dd + 3][rA] = a3;
            sm.p.Rs[dd][rB] = b0; sm.p.Rs[dd + 1][rB] = b1;
            sm.p.Rs[dd + 2][rB] = b2; sm.p.Rs[dd + 3][rB] = b3;
        }
    }
    __syncthreads();

    // ---- Pooling ----
    const int d  = t & 31;
    const int jg = t >> 5;                 // 0..7, 16 j's each

    ull r2[8];
#pragma unroll
    for (int jj = 0; jj < 8; jj++)
        r2[jj] = *(const ull*)&sm.p.Rs[d][jg * 16 + 2 * jj];

    const ull ABSMASK = 0x7FFFFFFF7FFFFFFFULL;
    ull acc[4] = {0ULL, 0ULL, 0ULL, 0ULL};

#pragma unroll 2
    for (int i = 0; i < SEQ; i++) {
        ull l2; DUP_F32X2(l2, sm.p.Ls[i][d]);
#pragma unroll
        for (int jj = 0; jj < 8; jj++) {
            ull s;
            ADD_F32X2(s, l2, r2[jj]);
            s &= ABSMASK;                          // packed |.| (alu pipe)
            ADD_F32X2(acc[jj & 3], acc[jj & 3], s);
        }
    }

    float asum = 0.f;
#pragma unroll
    for (int q = 0; q < 4; q++) {
        F2U u; u.u = acc[q];
        asum += u.f.x + u.f.y;
    }
    sm.p.red[jg][d] = asum;

    if (t < 32) {                          // sumL (warp 0)
        float s = 0.f;
#pragma unroll 8
        for (int i = 0; i < SEQ; i++) s += sm.p.Ls[i][t];
        sm.p.sLR[0][t] = s;
    } else if (t < 64) {                   // sumR (warp 1)
        int dq = t - 32;
        float s = 0.f;
#pragma unroll 8
        for (int j = 0; j < SEQ; j++) s += sm.p.Rs[dq][j];
        sm.p.sLR[1][dq] = s;
    }
    __syncthreads();

    if (t < 32) {
        float a = 0.f;
#pragma unroll
        for (int g = 0; g < 8; g++) a += sm.p.red[g][t];
        float lin = (float)SEQ * (sm.p.sLR[0][t] + sm.p.sLR[1][t]);
        sm.p.red[0][t] = 0.5f * (lin + a);   // final pooled chunk, in smem
    }
    __syncthreads();

    // ---- Output rank-32 update: thread t owns output column o = t ----
    {
        const float4* w = (const float4*)(Wrn + (size_t)t * D + d0);
        float accO = 0.f;
#pragma unroll
        for (int u = 0; u < 8; u++) {
            float4 wv = w[u];
            accO += sm.p.red[0][4 * u + 0] * wv.x
                  + sm.p.red[0][4 * u + 1] * wv.y
                  + sm.p.red[0][4 * u + 2] * wv.z
                  + sm.p.red[0][4 * u + 3] * wv.w;
        }
        atomicAdd(&out[b * D + t], accO);
    }
}

// ---------------------------------------------------------------------------
extern "C" void kernel_launch(void* const* d_in, const int* in_sizes, int n_in,
                              void* d_out, int out_size)
{
    const int*   X   = (const int*)  d_in[0];
    const float* emb = (const float*)d_in[1];
    const float* Wl  = (const float*)d_in[2];
    const float* bl  = (const float*)d_in[3];
    const float* Wr  = (const float*)d_in[4];
    const float* br  = (const float*)d_in[5];
    const float* Wrn = (const float*)d_in[6];
    const float* brn = (const float*)d_in[7];
    float* out = (float*)d_out;

    k_init<<<BATCH * D / 256, 256>>>(brn, out);
    k_main<<<dim3(D / 32, BATCH), 256>>>(X, emb, Wl, bl, Wr, br, Wrn, out);
}